// round 1
// baseline (speedup 1.0000x reference)
#include <cuda_runtime.h>
#include <cstdint>

// Counters: [0..2] = count(vol1==l) for l=1..3
//           [3..5] = count(vol2==l)
//           [6..8] = count(vol1==l && vol2==l)
__device__ unsigned int g_counts[9];

__global__ void zero_counts_kernel() {
    if (threadIdx.x < 9) g_counts[threadIdx.x] = 0u;
}

__global__ void __launch_bounds__(256) dice_count_kernel(
    const float4* __restrict__ a, const float4* __restrict__ b, int n_vec)
{
    unsigned int c0 = 0, c1 = 0, c2 = 0;   // vol1 label 1,2,3
    unsigned int d0 = 0, d1 = 0, d2 = 0;   // vol2 label 1,2,3
    unsigned int i0 = 0, i1 = 0, i2 = 0;   // intersections

    const int stride = gridDim.x * blockDim.x;
    int idx = blockIdx.x * blockDim.x + threadIdx.x;

    #pragma unroll 2
    for (; idx < n_vec; idx += stride) {
        float4 va = __ldcs(&a[idx]);
        float4 vb = __ldcs(&b[idx]);

        // lane-wise processing (exact float equality: labels are 0..3 exact)
        {
            bool m1 = (va.x == 1.0f), m2 = (va.x == 2.0f), m3 = (va.x == 3.0f);
            bool n1 = (vb.x == 1.0f), n2 = (vb.x == 2.0f), n3 = (vb.x == 3.0f);
            c0 += m1; c1 += m2; c2 += m3;
            d0 += n1; d1 += n2; d2 += n3;
            i0 += m1 & n1; i1 += m2 & n2; i2 += m3 & n3;
        }
        {
            bool m1 = (va.y == 1.0f), m2 = (va.y == 2.0f), m3 = (va.y == 3.0f);
            bool n1 = (vb.y == 1.0f), n2 = (vb.y == 2.0f), n3 = (vb.y == 3.0f);
            c0 += m1; c1 += m2; c2 += m3;
            d0 += n1; d1 += n2; d2 += n3;
            i0 += m1 & n1; i1 += m2 & n2; i2 += m3 & n3;
        }
        {
            bool m1 = (va.z == 1.0f), m2 = (va.z == 2.0f), m3 = (va.z == 3.0f);
            bool n1 = (vb.z == 1.0f), n2 = (vb.z == 2.0f), n3 = (vb.z == 3.0f);
            c0 += m1; c1 += m2; c2 += m3;
            d0 += n1; d1 += n2; d2 += n3;
            i0 += m1 & n1; i1 += m2 & n2; i2 += m3 & n3;
        }
        {
            bool m1 = (va.w == 1.0f), m2 = (va.w == 2.0f), m3 = (va.w == 3.0f);
            bool n1 = (vb.w == 1.0f), n2 = (vb.w == 2.0f), n3 = (vb.w == 3.0f);
            c0 += m1; c1 += m2; c2 += m3;
            d0 += n1; d1 += n2; d2 += n3;
            i0 += m1 & n1; i1 += m2 & n2; i2 += m3 & n3;
        }
    }

    // warp reduce all 9 counters
    unsigned int v[9] = {c0, c1, c2, d0, d1, d2, i0, i1, i2};
    #pragma unroll
    for (int k = 0; k < 9; ++k) {
        #pragma unroll
        for (int off = 16; off > 0; off >>= 1)
            v[k] += __shfl_down_sync(0xFFFFFFFFu, v[k], off);
    }

    // block reduce via shared atomics, then one global atomic per counter
    __shared__ unsigned int s[9];
    if (threadIdx.x < 9) s[threadIdx.x] = 0u;
    __syncthreads();
    if ((threadIdx.x & 31) == 0) {
        #pragma unroll
        for (int k = 0; k < 9; ++k) atomicAdd(&s[k], v[k]);
    }
    __syncthreads();
    if (threadIdx.x < 9) atomicAdd(&g_counts[threadIdx.x], s[threadIdx.x]);
}

__global__ void dice_final_kernel(float* __restrict__ out) {
    const float eps = 1.1920928955078125e-07f;  // FLT_EPSILON, matches np.finfo(float32).eps
    float sum = 0.0f;
    #pragma unroll
    for (int l = 0; l < 3; ++l) {
        float inter = (float)g_counts[6 + l];
        float bot   = (float)g_counts[l] + (float)g_counts[3 + l];
        sum += (2.0f * inter) / (bot + eps);
    }
    out[0] = 1.0f - sum * (1.0f / 3.0f);
}

extern "C" void kernel_launch(void* const* d_in, const int* in_sizes, int n_in,
                              void* d_out, int out_size)
{
    const float4* a = (const float4*)d_in[0];
    const float4* b = (const float4*)d_in[1];
    float* out = (float*)d_out;

    int n = in_sizes[0];        // 512^3 = 134217728, divisible by 4
    int n_vec = n >> 2;

    zero_counts_kernel<<<1, 32>>>();

    const int threads = 256;
    const int blocks  = 152 * 8;   // full GB300 chip (152 SMs), 8 CTAs/SM
    dice_count_kernel<<<blocks, threads>>>(a, b, n_vec);

    dice_final_kernel<<<1, 1>>>(out);
}